// round 12
// baseline (speedup 1.0000x reference)
#include <cuda_runtime.h>

// EdgeAugmentation, single-node, fully join-free, stateless (v9).
// LayerNorm over a singleton axis => every score == beta => stable top_k picks
// the first TOPK row-major (i,j) per graph that are neither an existing
// same-graph edge nor diagonal. Output buffer is float32.
//
// Reduction (validated R9/R10): the first 16 free cells of every graph lie in
// rows 0..7 (~960 free vs 16 needed), so only edges with src in
// [128b, 128b+8) matter for graph b.
//
// 128 blocks x 256 threads, ONE kernel, no global scratch, no barrier, no
// graph edge, no replay-state:
//   blocks 64..127: pure copy -- one int4 packet pair per thread
//                   (int32 edge_index -> float32 output rows).
//   blocks 0..63:   scan the full src row (L2-broadcast across blocks); edges
//                   hitting graph b rows 0..7 fetch their dst scalar and OR a
//                   bit into a 32-word SHARED bitmap; warp 0 then rank-scans
//                   the free bitmap and emits the first 16 cells.

#define E_EDGES 65536
#define BQ      64
#define TOPK_K  16
#define AUG     (E_EDGES + BQ * TOPK_K)   // 66560 columns in aug_edge_index
#define KROWS   8                          // rows retained per graph
#define KWORDS  32                         // KROWS*128/32 bitmap words

__device__ __forceinline__ int4 ldcg_int4(const int4* p) {
    int4 v;
    asm volatile("ld.global.cg.v4.s32 {%0,%1,%2,%3}, [%4];"
                 : "=r"(v.x), "=r"(v.y), "=r"(v.z), "=r"(v.w) : "l"(p));
    return v;
}

__global__ void __launch_bounds__(256, 1)
fused_kernel(const int* __restrict__ ei, float* __restrict__ out, int write_count) {
    const int b = blockIdx.x;
    const int t = threadIdx.x;      // 0..255

    if (b >= BQ) {
        // ---- Copy block: slice (b-64) of edge_index -> float output ----
        const int p4 = ((b - BQ) << 8) + t;           // 0..16383
        int4 s4 = ldcg_int4((const int4*)ei + p4);
        int4 d4 = ldcg_int4((const int4*)(ei + E_EDGES) + p4);
        ((float4*)out)[p4] =
            make_float4((float)s4.x, (float)s4.y, (float)s4.z, (float)s4.w);
        ((float4*)(out + AUG))[p4] =
            make_float4((float)d4.x, (float)d4.y, (float)d4.z, (float)d4.w);
        if (p4 == 0 && write_count)
            out[2 * AUG] = (float)(BQ * TOPK_K);      // added_count
        return;
    }

    // ---- Scan block: build graph b's rows-0..7 bitmap in shared memory ----
    __shared__ unsigned bm[KWORDS];
    if (t < KWORDS) bm[t] = 0u;
    __syncthreads();

    const int boff = b << 7;                          // graph b node base

    #pragma unroll 8
    for (int i = 0; i < E_EDGES / 4 / 256; i++) {     // 64 iterations
        const int p4 = (i << 8) + t;
        int4 s4 = ldcg_int4((const int4*)ei + p4);
        int ss[4] = { s4.x, s4.y, s4.z, s4.w };
        #pragma unroll
        for (int k = 0; k < 4; k++) {
            unsigned row = (unsigned)(ss[k] - boff);
            if (row < KROWS) {                        // graph b AND row < 8
                int d = __ldcg(ei + E_EDGES + (p4 << 2) + k);
                unsigned col = (unsigned)(d - boff);
                if (col < 128u) {                     // same-graph edge
                    unsigned bit = (row << 7) | col;
                    atomicOr(&bm[bit >> 5], 1u << (bit & 31));
                }
            }
        }
    }
    __syncthreads();

    // ---- Warp 0: rank-scan the free bitmap; emit first TOPK cells ----
    if (t >= 32) return;
    const int lane = t;

    unsigned m = ~bm[lane];
    // Clear the (at most one) diagonal bit in this word: positions p = 129*i.
    int lo = lane << 5;
    int p  = ((lo + 128) / 129) * 129;
    if (p < lo + 32) m &= ~(1u << (p - lo));

    int c = __popc(m);

    // Inclusive warp scan of popcounts -> exclusive rank.
    int v = c;
    #pragma unroll
    for (int off = 1; off < 32; off <<= 1) {
        int x = __shfl_up_sync(0xffffffffu, v, off);
        if (lane >= off) v += x;
    }
    int r = v - c;                                    // exclusive rank

    if (r < TOPK_K && m) {
        unsigned mm = m;
        while (mm && r < TOPK_K) {
            int bi = __ffs(mm) - 1;
            mm &= mm - 1;
            int bitpos = lo + bi;
            out[E_EDGES + b * TOPK_K + r]       = (float)(boff + (bitpos >> 7));
            out[AUG + E_EDGES + b * TOPK_K + r] = (float)(boff + (bitpos & 127));
            r++;
        }
    }
}

extern "C" void kernel_launch(void* const* d_in, const int* in_sizes, int n_in,
                              void* d_out, int out_size) {
    // Locate edge_index by its unique element count (2 * E = 131072, int32).
    const int* ei = nullptr;
    for (int i = 0; i < n_in; i++) {
        if (in_sizes[i] == 2 * E_EDGES) { ei = (const int*)d_in[i]; break; }
    }
    float* out = (float*)d_out;

    fused_kernel<<<2 * BQ, 256>>>(ei, out, (out_size > 2 * AUG) ? 1 : 0);
}

// round 13
// speedup vs baseline: 1.6827x; 1.6827x over previous
#include <cuda_runtime.h>

// EdgeAugmentation, two-node formulation, minimal tail (v10).
// LayerNorm over a singleton axis => every score == beta => stable top_k picks
// the first TOPK row-major (i,j) per graph that are neither an existing
// same-graph edge nor diagonal. Output buffer is float32.
//
// Reduction (validated R9/R10): the first 16 free cells of every graph lie in
// rows 0..7 (~960 free vs 16 needed), so only edges with src%128 < 8 touch
// the 32-word per-graph bitmap (~4K REDs total).
//
// Node A (64x256): copy one int4 packet pair per thread (int32 edge_index ->
//   float32 output rows) AND issue filtered REDs into the global per-graph
//   bitmap. Copy overlaps the RED stream; no barrier -- kernel just ends.
// Node B (2x1024): warp w of block b scans graph 32b+w's bitmap (REDs visible
//   across the graph edge), emits the first 16 free cells, zeroes the slice
//   (restores the all-zero precondition for the next replay; device globals
//   are zero-init at load, so call #1 is clean too).

#define E_EDGES 65536
#define BQ      64
#define TOPK_K  16
#define AUG     (E_EDGES + BQ * TOPK_K)   // 66560 columns in aug_edge_index
#define KROWS   8                          // rows retained per graph
#define KWORDS  32                         // KROWS*128/32 bitmap words per graph

__device__ unsigned g_exist[BQ][KWORDS];   // zero-init; restored to zero each run

__device__ __forceinline__ int4 ldcg_int4(const int4* p) {
    int4 v;
    asm volatile("ld.global.cg.v4.s32 {%0,%1,%2,%3}, [%4];"
                 : "=r"(v.x), "=r"(v.y), "=r"(v.z), "=r"(v.w) : "l"(p));
    return v;
}

// ---- Node A: copy + filtered bitmap build ----
__global__ void __launch_bounds__(256, 1)
build_kernel(const int* __restrict__ ei, float* __restrict__ out, int write_count) {
    const int p4 = (blockIdx.x << 8) + threadIdx.x;   // 0..16383
    int4 s4 = ldcg_int4((const int4*)ei + p4);
    int4 d4 = ldcg_int4((const int4*)(ei + E_EDGES) + p4);

    // Bulk copy (independent of bitmap; overlaps the RED stream below).
    ((float4*)out)[p4] =
        make_float4((float)s4.x, (float)s4.y, (float)s4.z, (float)s4.w);
    ((float4*)(out + AUG))[p4] =
        make_float4((float)d4.x, (float)d4.y, (float)d4.z, (float)d4.w);

    int ss[4] = { s4.x, s4.y, s4.z, s4.w };
    int dd[4] = { d4.x, d4.y, d4.z, d4.w };
    #pragma unroll
    for (int k = 0; k < 4; k++) {
        int g   = ss[k] >> 7;
        int row = ss[k] & 127;
        if (row < KROWS && (dd[k] >> 7) == g) {
            unsigned bit = ((unsigned)row << 7) | (unsigned)(dd[k] & 127);
            atomicOr(&g_exist[g][bit >> 5], 1u << (bit & 31));   // RED
        }
    }
    if (p4 == 0 && write_count)
        out[2 * AUG] = (float)(BQ * TOPK_K);          // added_count
}

// ---- Node B: scan-only, 64 warps total ----
__global__ void __launch_bounds__(1024, 1)
emit_kernel(float* __restrict__ out) {
    const int g    = (blockIdx.x << 5) + (threadIdx.x >> 5);  // graph 0..63
    const int lane = threadIdx.x & 31;
    const int boff = g << 7;

    unsigned w = __ldcg(&g_exist[g][lane]);            // 1 word/lane
    g_exist[g][lane] = 0u;                             // restore precondition

    unsigned m = ~w;
    // Clear the (at most one) diagonal bit in this word: positions p = 129*i.
    int lo = lane << 5;
    int p  = ((lo + 128) / 129) * 129;
    if (p < lo + 32) m &= ~(1u << (p - lo));

    int c = __popc(m);

    // Inclusive warp scan of popcounts -> exclusive rank.
    int v = c;
    #pragma unroll
    for (int off = 1; off < 32; off <<= 1) {
        int x = __shfl_up_sync(0xffffffffu, v, off);
        if (lane >= off) v += x;
    }
    int r = v - c;                                     // exclusive rank

    if (r < TOPK_K && m) {
        unsigned mm = m;
        while (mm && r < TOPK_K) {
            int bi = __ffs(mm) - 1;
            mm &= mm - 1;
            int bitpos = lo + bi;
            out[E_EDGES + g * TOPK_K + r]       = (float)(boff + (bitpos >> 7));
            out[AUG + E_EDGES + g * TOPK_K + r] = (float)(boff + (bitpos & 127));
            r++;
        }
    }
}

extern "C" void kernel_launch(void* const* d_in, const int* in_sizes, int n_in,
                              void* d_out, int out_size) {
    // Locate edge_index by its unique element count (2 * E = 131072, int32).
    const int* ei = nullptr;
    for (int i = 0; i < n_in; i++) {
        if (in_sizes[i] == 2 * E_EDGES) { ei = (const int*)d_in[i]; break; }
    }
    float* out = (float*)d_out;

    build_kernel<<<64, 256>>>(ei, out, (out_size > 2 * AUG) ? 1 : 0);
    emit_kernel<<<2, 1024>>>(out);
}